// round 1
// baseline (speedup 1.0000x reference)
#include <cuda_runtime.h>

#define P 45
#define PPAD 48
#define BPB 8
#define TPB (BPB * PPAD)   // 384 threads
#define NITER 20
#define SIG_ELEMS (BPB * P * P)  // 16200

// Shared layout (floats):
//   sig_sh : [BPB][P][PPAD]   = 17280
//   w_sh   : [BPB][PPAD]      = 384
//   part   : [2][BPB][4]      = 64
#define SMEM_FLOATS (BPB * P * PPAD + BPB * PPAD + 2 * BPB * 4)

__global__ __launch_bounds__(TPB, 2)
void drb_kernel(const float* __restrict__ sigma,
                const float* __restrict__ beta,
                const float* __restrict__ wprev,
                const float* __restrict__ lls,
                const float* __restrict__ llt,
                float* __restrict__ out,
                int B)
{
    extern __shared__ float sh[];
    float* sig_sh = sh;                         // [BPB][P][PPAD]
    float* w_sh   = sh + BPB * P * PPAD;        // [BPB][PPAD]
    float* part   = w_sh + BPB * PPAD;          // [2][BPB][4]

    const int t     = threadIdx.x;
    const int bl    = t / PPAD;        // batch-in-block 0..7
    const int row   = t % PPAD;        // 0..47 (45..47 idle)
    const int batch = blockIdx.x * BPB + bl;
    const bool active = (row < P) && (batch < B);

    // ---- Stage sigma coalesced into padded shared ----
    const float* gs = sigma + (size_t)blockIdx.x * SIG_ELEMS;
    const int nb_rem = B - blockIdx.x * BPB;
    if (nb_rem >= BPB) {
        const float4* gs4 = (const float4*)gs;
        for (int i = t; i < SIG_ELEMS / 4; i += TPB) {
            float4 v = gs4[i];
            int f = i * 4;
            #pragma unroll
            for (int e = 0; e < 4; e++) {
                int fe = f + e;
                int bb = fe / (P * P);
                int r  = (fe % (P * P)) / P;
                int c  = fe % P;
                float val = (e == 0) ? v.x : (e == 1) ? v.y : (e == 2) ? v.z : v.w;
                sig_sh[(bb * P + r) * PPAD + c] = val;
            }
        }
    } else {
        int tot = nb_rem * P * P;
        for (int i = t; i < tot; i += TPB) {
            int bb = i / (P * P);
            int r  = (i % (P * P)) / P;
            int c  = i % P;
            sig_sh[(bb * P + r) * PPAD + c] = gs[i];
        }
    }
    __syncthreads();

    // ---- Copy my row into registers (padded to 48 -> 12 float4) ----
    float4 srow[12];
    float beta_i = 0.f, wp_i = 0.f;
    if (active) {
        float* rbase = &sig_sh[(bl * P + row) * PPAD];
        rbase[P]     = 0.f;
        rbase[P + 1] = 0.f;
        rbase[P + 2] = 0.f;
        #pragma unroll
        for (int k = 0; k < 12; k++) srow[k] = ((const float4*)rbase)[k];
        beta_i = beta[(size_t)batch * P + row];
        wp_i   = wprev[(size_t)batch * P + row];
    } else {
        #pragma unroll
        for (int k = 0; k < 12; k++) srow[k] = make_float4(0.f, 0.f, 0.f, 0.f);
    }

    const float lam_s  = expf(lls[0]);
    const float lam_t2 = 2.f * expf(llt[0]);

    float w_i = active ? (1.0f / (float)P) : 0.f;
    w_sh[bl * PPAD + row] = w_i;
    __syncthreads();

    const float4* w4 = (const float4*)&w_sh[bl * PPAD];
    const int seg = row >> 4;   // 0..2
    float* part0 = part + bl * 4;
    float* part1 = part + BPB * 4 + bl * 4;

    for (int it = 0; it < NITER; it++) {
        // Sw = sigma_row . w
        float a0 = 0.f, a1 = 0.f, a2 = 0.f, a3 = 0.f;
        #pragma unroll
        for (int k = 0; k < 12; k++) {
            float4 wv = w4[k];
            a0 = fmaf(srow[k].x, wv.x, a0);
            a1 = fmaf(srow[k].y, wv.y, a1);
            a2 = fmaf(srow[k].z, wv.z, a2);
            a3 = fmaf(srow[k].w, wv.w, a3);
        }
        float Sw = (a0 + a1) + (a2 + a3);

        float sg = (float)((w_i > 0.f) - (w_i < 0.f));
        float g  = 2.f * Sw - beta_i + lam_s * sg + lam_t2 * (w_i - wp_i);
        float v  = w_i - 0.05f * g;
        v = fminf(fmaxf(v, 0.f), 0.15f);
        if (!active) v = 0.f;

        // ---- sum #1 over batch (16-lane butterfly + 3 segment partials) ----
        float pv = v;
        pv += __shfl_xor_sync(0xffffffffu, pv, 1, 16);
        pv += __shfl_xor_sync(0xffffffffu, pv, 2, 16);
        pv += __shfl_xor_sync(0xffffffffu, pv, 4, 16);
        pv += __shfl_xor_sync(0xffffffffu, pv, 8, 16);
        if ((row & 15) == 0) part0[seg] = pv;
        __syncthreads();
        float s1 = part0[0] + part0[1] + part0[2];

        float u = __fdividef(v, s1 + 1e-8f);
        u = fminf(fmaxf(u, 0.f), 0.15f);
        if (!active) u = 0.f;

        // ---- sum #2 ----
        float qv = u;
        qv += __shfl_xor_sync(0xffffffffu, qv, 1, 16);
        qv += __shfl_xor_sync(0xffffffffu, qv, 2, 16);
        qv += __shfl_xor_sync(0xffffffffu, qv, 4, 16);
        qv += __shfl_xor_sync(0xffffffffu, qv, 8, 16);
        if ((row & 15) == 0) part1[seg] = qv;
        __syncthreads();
        float s2 = part1[0] + part1[1] + part1[2];

        w_i = __fdividef(u, s2 + 1e-8f);
        w_sh[bl * PPAD + row] = active ? w_i : 0.f;
        __syncthreads();
    }

    if (active) out[(size_t)batch * P + row] = w_i;
}

extern "C" void kernel_launch(void* const* d_in, const int* in_sizes, int n_in,
                              void* d_out, int out_size)
{
    const float* sigma = (const float*)d_in[0];
    const float* beta  = (const float*)d_in[1];
    const float* wprev = (const float*)d_in[2];
    const float* lls   = (const float*)d_in[3];
    const float* llt   = (const float*)d_in[4];
    float* out = (float*)d_out;

    int B = in_sizes[1] / P;
    int grid = (B + BPB - 1) / BPB;
    size_t smem = SMEM_FLOATS * sizeof(float);

    cudaFuncSetAttribute(drb_kernel,
                         cudaFuncAttributeMaxDynamicSharedMemorySize,
                         (int)smem);
    drb_kernel<<<grid, TPB, smem>>>(sigma, beta, wprev, lls, llt, out, B);
}

// round 3
// speedup vs baseline: 1.1656x; 1.1656x over previous
#include <cuda_runtime.h>

#define P 45
#define PPAD 48
#define BPB 2
#define TPB (BPB * PPAD)   // 96 threads
#define NITER 20
#define SIG_ELEMS (BPB * P * P)  // 4050

// Shared layout (floats):
//   sig_sh : [BPB][P][PPAD]
//   w_sh   : [BPB][PPAD]
//   part   : [2][BPB][4]   (16B aligned)
#define SMEM_FLOATS (BPB * P * PPAD + BPB * PPAD + 2 * BPB * 4)

typedef unsigned long long ull;

__device__ __forceinline__ void ffma2(ull& d, ull a, ull b) {
    asm("fma.rn.f32x2 %0, %1, %2, %0;" : "+l"(d) : "l"(a), "l"(b));
}
__device__ __forceinline__ ull fadd2(ull a, ull b) {
    ull d;
    asm("add.rn.f32x2 %0, %1, %2;" : "=l"(d) : "l"(a), "l"(b));
    return d;
}
__device__ __forceinline__ void lds_v2u64(ull& a, ull& b, unsigned saddr) {
    asm volatile("ld.shared.v2.b64 {%0,%1},[%2];" : "=l"(a), "=l"(b) : "r"(saddr));
}

__global__ __launch_bounds__(TPB, 8)
void drb_kernel(const float* __restrict__ sigma,
                const float* __restrict__ beta,
                const float* __restrict__ wprev,
                const float* __restrict__ lls,
                const float* __restrict__ llt,
                float* __restrict__ out,
                int B)
{
    extern __shared__ float sh[];
    float* sig_sh = sh;                         // [BPB][P][PPAD]
    float* w_sh   = sh + BPB * P * PPAD;        // [BPB][PPAD]
    float* part   = w_sh + BPB * PPAD;          // [2][BPB][4]

    const int t     = threadIdx.x;
    const int bl    = t / PPAD;        // 0..1
    const int row   = t % PPAD;        // 0..47 (45..47 idle)
    const int batch = blockIdx.x * BPB + bl;
    const bool active = (row < P) && (batch < B);

    // ---- Stage sigma coalesced into padded shared (float2: 16200B block
    //      stride is 8B-aligned for every block, never 16B) ----
    const float* gs = sigma + (size_t)blockIdx.x * SIG_ELEMS;
    const int nb_rem = B - blockIdx.x * BPB;
    if (nb_rem >= BPB) {
        const float2* gs2 = (const float2*)gs;
        #pragma unroll 4
        for (int i = t; i < SIG_ELEMS / 2; i += TPB) {
            float2 v = gs2[i];
            int f = i * 2;
            int bb0 = f / (P * P);
            int rr0 = (f % (P * P)) / P;
            int cc0 = f % P;
            sig_sh[(bb0 * P + rr0) * PPAD + cc0] = v.x;
            int f1 = f + 1;
            int bb1 = f1 / (P * P);
            int rr1 = (f1 % (P * P)) / P;
            int cc1 = f1 % P;
            sig_sh[(bb1 * P + rr1) * PPAD + cc1] = v.y;
        }
    } else {
        int tot = nb_rem * P * P;
        for (int i = t; i < tot; i += TPB) {
            int bb = i / (P * P);
            int r  = (i % (P * P)) / P;
            int c  = i % P;
            sig_sh[(bb * P + r) * PPAD + c] = gs[i];
        }
    }
    __syncthreads();

    // ---- Copy my row into 64-bit packed registers (48 floats -> 24 x f32x2) ----
    ull srow2[24];
    float beta_i = 0.f, wp_i = 0.f;
    if (active) {
        float* rbase = &sig_sh[(bl * P + row) * PPAD];
        rbase[P]     = 0.f;
        rbase[P + 1] = 0.f;
        rbase[P + 2] = 0.f;
        unsigned rs = (unsigned)__cvta_generic_to_shared(rbase);
        #pragma unroll
        for (int k = 0; k < 12; k++)
            lds_v2u64(srow2[2 * k], srow2[2 * k + 1], rs + k * 16);
        beta_i = beta[(size_t)batch * P + row];
        wp_i   = wprev[(size_t)batch * P + row];
    } else {
        #pragma unroll
        for (int k = 0; k < 24; k++) srow2[k] = 0ull;
    }

    const float lam_s  = expf(lls[0]);
    const float lam_t2 = 2.f * expf(llt[0]);
    // folded constants:  v = k_w*w - 0.1*Sw + (w>0 ? c_pos : c_base)
    const float k_w    = 1.f - 0.05f * lam_t2;
    const float c_base = 0.05f * fmaf(lam_t2, wp_i, beta_i);
    const float c_pos  = c_base - 0.05f * lam_s;

    float w_i = active ? (1.0f / (float)P) : 0.f;
    w_sh[bl * PPAD + row] = w_i;

    const unsigned w_saddr =
        (unsigned)__cvta_generic_to_shared(&w_sh[bl * PPAD]);
    const int seg = row >> 4;   // 0..2
    float* part0 = part + bl * 4;
    float* part1 = part + BPB * 4 + bl * 4;
    __syncthreads();

    for (int it = 0; it < NITER; it++) {
        // ---- Sw = sigma_row . w  (packed f32x2 FMAs) ----
        ull acc0 = 0ull, acc1 = 0ull, acc2 = 0ull, acc3 = 0ull;
        #pragma unroll
        for (int k = 0; k < 12; k++) {
            ull w0, w1;
            lds_v2u64(w0, w1, w_saddr + k * 16);
            if (k & 1) {
                ffma2(acc2, srow2[2 * k], w0);
                ffma2(acc3, srow2[2 * k + 1], w1);
            } else {
                ffma2(acc0, srow2[2 * k], w0);
                ffma2(acc1, srow2[2 * k + 1], w1);
            }
        }
        ull stot = fadd2(fadd2(acc0, acc2), fadd2(acc1, acc3));
        float slo, shi;
        asm("mov.b64 {%0,%1},%2;" : "=f"(slo), "=f"(shi) : "l"(stot));
        float Sw = slo + shi;

        // ---- gradient step (folded) ----
        float c_sel = (w_i > 0.f) ? c_pos : c_base;
        float v = fmaf(k_w, w_i, fmaf(-0.1f, Sw, c_sel));
        v = fminf(fmaxf(v, 0.f), 0.15f);   // inactive lanes: v==0 naturally

        // ---- sum #1 over batch (16-lane butterfly + 3 segment partials) ----
        float pv = v;
        pv += __shfl_xor_sync(0xffffffffu, pv, 1, 16);
        pv += __shfl_xor_sync(0xffffffffu, pv, 2, 16);
        pv += __shfl_xor_sync(0xffffffffu, pv, 4, 16);
        pv += __shfl_xor_sync(0xffffffffu, pv, 8, 16);
        if ((row & 15) == 0) part0[seg] = pv;
        __syncthreads();
        float4 p0 = *(const float4*)part0;
        float s1 = (p0.x + p0.y) + p0.z;

        float u = __fdividef(v, s1 + 1e-8f);
        u = fminf(fmaxf(u, 0.f), 0.15f);

        // ---- sum #2 ----
        float qv = u;
        qv += __shfl_xor_sync(0xffffffffu, qv, 1, 16);
        qv += __shfl_xor_sync(0xffffffffu, qv, 2, 16);
        qv += __shfl_xor_sync(0xffffffffu, qv, 4, 16);
        qv += __shfl_xor_sync(0xffffffffu, qv, 8, 16);
        if ((row & 15) == 0) part1[seg] = qv;
        __syncthreads();
        float4 p1 = *(const float4*)part1;
        float s2 = (p1.x + p1.y) + p1.z;

        w_i = __fdividef(u, s2 + 1e-8f);
        w_sh[bl * PPAD + row] = w_i;
        __syncthreads();
    }

    if (active) out[(size_t)batch * P + row] = w_i;
}

extern "C" void kernel_launch(void* const* d_in, const int* in_sizes, int n_in,
                              void* d_out, int out_size)
{
    const float* sigma = (const float*)d_in[0];
    const float* beta  = (const float*)d_in[1];
    const float* wprev = (const float*)d_in[2];
    const float* lls   = (const float*)d_in[3];
    const float* llt   = (const float*)d_in[4];
    float* out = (float*)d_out;

    int B = in_sizes[1] / P;
    int grid = (B + BPB - 1) / BPB;
    size_t smem = SMEM_FLOATS * sizeof(float);

    drb_kernel<<<grid, TPB, smem>>>(sigma, beta, wprev, lls, llt, out, B);
}